// round 1
// baseline (speedup 1.0000x reference)
#include <cuda_runtime.h>

// Problem constants (B, D, H) = (8192, 64, 256)
#define BATCH 8192
#define DD 64
#define HH 256

// Dynamic smem layout (floats):
//   s_u  [16384] : phase1 = W1dT[k][i] = W1[i][k]*d1[k]; phase2 = W3[l][o]
//   s_A  [17408] : As[l][i], row stride 68 (padding: 68 mod 32 == 4 -> mild conflicts on store, clean float4 loads)
//   s_x  [64], s_h1[256], s_d1[256]
#define SM_U_OFF   0
#define SM_A_OFF   16384
#define SM_X_OFF   (16384 + 17408)
#define SM_H1_OFF  (SM_X_OFF + 64)
#define SM_D1_OFF  (SM_H1_OFF + 256)
#define SM_FLOATS  (SM_D1_OFF + 256)

__global__ __launch_bounds__(256, 1)
void jac_kernel(const float* __restrict__ x,  const float* __restrict__ W1,
                const float* __restrict__ b1, const float* __restrict__ W2,
                const float* __restrict__ b2, const float* __restrict__ W3,
                const float* __restrict__ b3, float* __restrict__ out)
{
    extern __shared__ float sm[];
    float* s_u  = sm + SM_U_OFF;
    float* s_A  = sm + SM_A_OFF;
    float* s_x  = sm + SM_X_OFF;
    float* s_h1 = sm + SM_H1_OFF;
    float* s_d1 = sm + SM_D1_OFF;

    const int tid = threadIdx.x;       // tid == hidden index j == column l
    const int b   = blockIdx.x;

    if (tid < DD) s_x[tid] = x[b * DD + tid];
    __syncthreads();

    // ---- forward layer 1: h1 = tanh(x @ W1 + b1), d1 = 1 - h1^2 ----
    {
        float a = b1[tid];
        #pragma unroll 16
        for (int i = 0; i < DD; i++) a += s_x[i] * W1[i * HH + tid];
        float t = tanhf(a);
        s_h1[tid] = t;
        s_d1[tid] = 1.0f - t * t;
    }
    __syncthreads();

    // ---- forward layer 2: d2 (each thread keeps its own d2[l] in a register) ----
    float d2l;
    {
        float a = b2[tid];
        #pragma unroll 8
        for (int k = 0; k < HH; k++) a += s_h1[k] * W2[k * HH + tid];
        float t = tanhf(a);
        d2l = 1.0f - t * t;
    }

    // ---- build W1dT[k][i] = W1[i][k] * d1[k] in smem ----
    for (int idx = tid; idx < DD * HH; idx += 256) {
        int k = idx >> 6;
        int i = idx & 63;
        s_u[idx] = W1[i * HH + k] * s_d1[k];
    }
    __syncthreads();

    // ---- phase 1: A[i] = sum_k W1dT[k][i] * W2[k][l],  l = tid ----
    float A[DD];
    #pragma unroll
    for (int i = 0; i < DD; i++) A[i] = 0.0f;

    const float* w2col = W2 + tid;
    #pragma unroll 4
    for (int k = 0; k < HH; k++) {
        float w2 = w2col[k * HH];                       // coalesced, L2-resident
        const float4* u = (const float4*)(s_u + k * DD); // broadcast reads
        #pragma unroll
        for (int j = 0; j < 16; j++) {
            float4 v = u[j];
            A[4*j+0] += v.x * w2;
            A[4*j+1] += v.y * w2;
            A[4*j+2] += v.z * w2;
            A[4*j+3] += v.w * w2;
        }
    }

    // ---- scale by d2[l], store As[l][i] (row stride 68) ----
    {
        float4* dst = (float4*)(s_A + tid * 68);
        #pragma unroll
        for (int j = 0; j < 16; j++) {
            dst[j] = make_float4(A[4*j+0] * d2l, A[4*j+1] * d2l,
                                 A[4*j+2] * d2l, A[4*j+3] * d2l);
        }
    }
    __syncthreads();

    // ---- reuse s_u for W3[l][o] ----
    for (int idx = tid; idx < HH * DD; idx += 256) s_u[idx] = W3[idx];
    __syncthreads();

    // ---- phase 2: J^T[i][o] = sum_l As[l][i] * W3[l][o], 4x4 register tile ----
    const int ti = tid & 15;   // i block: [4*ti, 4*ti+3]
    const int to = tid >> 4;   // o block: [4*to, 4*to+3]
    float acc[4][4];
    #pragma unroll
    for (int a_ = 0; a_ < 4; a_++)
        #pragma unroll
        for (int c_ = 0; c_ < 4; c_++) acc[a_][c_] = 0.0f;

    #pragma unroll 4
    for (int l = 0; l < HH; l++) {
        float4 av = *(const float4*)(s_A + l * 68 + 4 * ti);
        float4 wv = *(const float4*)(s_u + l * DD + 4 * to);
        float a0 = av.x, a1 = av.y, a2 = av.z, a3 = av.w;
        float w0 = wv.x, w1 = wv.y, w2v = wv.z, w3v = wv.w;
        acc[0][0] += a0*w0;  acc[0][1] += a0*w1;  acc[0][2] += a0*w2v;  acc[0][3] += a0*w3v;
        acc[1][0] += a1*w0;  acc[1][1] += a1*w1;  acc[1][2] += a1*w2v;  acc[1][3] += a1*w3v;
        acc[2][0] += a2*w0;  acc[2][1] += a2*w1;  acc[2][2] += a2*w2v;  acc[2][3] += a2*w3v;
        acc[3][0] += a3*w0;  acc[3][1] += a3*w1;  acc[3][2] += a3*w2v;  acc[3][3] += a3*w3v;
    }

    // ---- write out[b][o][i] = J^T[i][o]; float4 along i, coalesced across ti ----
    float* ob = out + (size_t)b * (DD * DD);
    #pragma unroll
    for (int oo = 0; oo < 4; oo++) {
        float4 v = make_float4(acc[0][oo], acc[1][oo], acc[2][oo], acc[3][oo]);
        *(float4*)(ob + (4 * to + oo) * DD + 4 * ti) = v;
    }
    (void)b3; // b3 does not affect the Jacobian
}

extern "C" void kernel_launch(void* const* d_in, const int* in_sizes, int n_in,
                              void* d_out, int out_size)
{
    const float* x  = (const float*)d_in[0];
    const float* W1 = (const float*)d_in[1];
    const float* b1 = (const float*)d_in[2];
    const float* W2 = (const float*)d_in[3];
    const float* b2 = (const float*)d_in[4];
    const float* W3 = (const float*)d_in[5];
    const float* b3 = (const float*)d_in[6];
    float* out = (float*)d_out;

    size_t smem = (size_t)SM_FLOATS * sizeof(float);   // ~137.5 KB
    cudaFuncSetAttribute(jac_kernel, cudaFuncAttributeMaxDynamicSharedMemorySize, (int)smem);
    jac_kernel<<<BATCH, 256, smem>>>(x, W1, b1, W2, b2, W3, b3, out);
}

// round 2
// speedup vs baseline: 3.3996x; 3.3996x over previous
#include <cuda_runtime.h>
#include <cstdint>

#define BATCH 8192
#define DDIM  64
#define HDIM  256
#define NCTA  148

// shared memory word-layout
#define AST   260            // Asm/Tsm row stride (words): bank = 4g+tig -> conflict-free frags
#define BST   264            // W2-chunk row stride: bank = 8*tig+g -> conflict-free
#define W3ST  264            // W3t row stride (transposed W3, [o][lperm])
#define JST   68             // J staging row stride

#define OFF_A   0                         // 64*260      = 16640
#define OFF_B   16640                     // 2*32*264    = 16896 (also W1 stage / J stage overlay)
#define BUFW    (32*BST)                  // 8448 words per chunk buffer
#define OFF_W3  (OFF_B + 2*BUFW)          // 33536, 64*264 = 16896
#define OFF_X   (OFF_W3 + 64*W3ST)        // 50432
#define OFF_H1  (OFF_X + 64)
#define OFF_D1  (OFF_H1 + 256)
#define OFF_D2  (OFF_D1 + 256)
#define SM_WORDS (OFF_D2 + 256)           // 51264 words = 205056 B

__device__ __forceinline__ uint32_t f2tf32(float f) {
    uint32_t u;
    asm("cvt.rna.tf32.f32 %0, %1;" : "=r"(u) : "f"(f));
    return u;
}

#define MMA_TF32(d, a0, a1, a2, a3, b0, b1)                                  \
    asm volatile(                                                            \
        "mma.sync.aligned.m16n8k8.row.col.f32.tf32.tf32.f32 "                \
        "{%0,%1,%2,%3}, {%4,%5,%6,%7}, {%8,%9}, {%0,%1,%2,%3};"              \
        : "+f"(d[0]), "+f"(d[1]), "+f"(d[2]), "+f"(d[3])                     \
        : "r"(a0), "r"(a1), "r"(a2), "r"(a3), "r"(b0), "r"(b1))

// permute k within its 8-group so fragment cols (t, t+4) become adjacent (LDS.64)
__device__ __forceinline__ int kperm(int k) {
    int r = k & 7;
    int p = (r < 4) ? (2 * r) : (2 * (r - 4) + 1);
    return (k & ~7) | p;
}

__global__ __launch_bounds__(256, 1)
void jac_tc_kernel(const float* __restrict__ x,  const float* __restrict__ W1,
                   const float* __restrict__ b1, const float* __restrict__ W2,
                   const float* __restrict__ b2, const float* __restrict__ W3,
                   float* __restrict__ out)
{
    extern __shared__ uint32_t smw[];
    uint32_t* smA  = smw + OFF_A;          // tf32 bits: A=W1d / later T'=T*d2
    uint32_t* smB  = smw + OFF_B;          // tf32 bits: W2 chunk double buffer
    float*    smBf = (float*)smB;          // fp32 views (W1 stage / J stage)
    uint32_t* smW3 = smw + OFF_W3;         // tf32 bits: W3 transposed+permuted
    float*    s_x  = (float*)(smw + OFF_X);
    float*    s_h1 = (float*)(smw + OFF_H1);
    float*    s_d1 = (float*)(smw + OFF_D1);
    float*    s_d2 = (float*)(smw + OFF_D2);

    const int tid  = threadIdx.x;
    const int lane = tid & 31;
    const int w    = tid >> 5;      // warp 0..7
    const int g    = lane >> 2;     // groupID 0..7
    const int tig  = lane & 3;      // thread-in-group 0..3
    const int kp_t = kperm(tid & 255); // permuted col for this thread's k=tid (A build)

    // ---- one-time: W3 -> smW3[o][lperm(l)] (tf32) ----
    for (int j = 0; j < 64; j++) {
        int idx = tid + 256 * j;           // 16384 elems
        int l = idx >> 6, o = idx & 63;
        smW3[o * W3ST + kperm(l)] = f2tf32(W3[idx]);
    }

    for (int b = blockIdx.x; b < BATCH; b += gridDim.x) {
        __syncthreads();   // protect J-stage reads / W3 init before W1 restage

        // ---- stage x, W1 (fp32) into smem ----
        if (tid < DDIM) s_x[tid] = x[b * DDIM + tid];
        {
            const float4* p = (const float4*)W1;
            #pragma unroll
            for (int j = 0; j < 16; j++) {
                int f = tid + 256 * j;                 // 4096 float4 = 64KB
                ((float4*)smBf)[f] = p[f];
            }
        }
        __syncthreads();

        // ---- forward layer 1: h1, d1 ----
        {
            float a = b1[tid];
            #pragma unroll 16
            for (int i = 0; i < DDIM; i++) a += s_x[i] * smBf[i * HDIM + tid];
            float t = tanhf(a);
            s_h1[tid] = t;
            s_d1[tid] = 1.0f - t * t;
        }
        __syncthreads();

        // ---- build A[i][k] = W1[i][k]*d1[k] (tf32, permuted cols) ----
        {
            float d1k = s_d1[tid];
            #pragma unroll 8
            for (int m = 0; m < 64; m++)
                smA[m * AST + kp_t] = f2tf32(smBf[m * HDIM + tid] * d1k);
        }
        float accH = b2[tid];      // forward layer-2 partial for l = tid
        __syncthreads();           // A ready, W1 stage area free

        // ---- GEMM1: T = A @ W2  (M=64, N=256, K=256), chunked K by 32 ----
        float acc1[4][4][4];
        #pragma unroll
        for (int mt = 0; mt < 4; mt++)
            #pragma unroll
            for (int nt = 0; nt < 4; nt++)
                #pragma unroll
                for (int c = 0; c < 4; c++) acc1[mt][nt][c] = 0.0f;

        float4 stg[8];
        {   // prologue: LDG chunk 0
            const float4* p = (const float4*)W2;
            #pragma unroll
            for (int j = 0; j < 8; j++) stg[j] = p[tid + 256 * j];
        }

        for (int c = 0; c < 8; c++) {
            uint32_t* buf = smB + (c & 1) * BUFW;
            // STS chunk c (convert to tf32)
            #pragma unroll
            for (int j = 0; j < 8; j++) {
                int f  = tid + 256 * j;
                int kk = f >> 6, c4 = (f & 63) << 2;
                uint4 q;
                q.x = f2tf32(stg[j].x); q.y = f2tf32(stg[j].y);
                q.z = f2tf32(stg[j].z); q.w = f2tf32(stg[j].w);
                *(uint4*)&buf[kk * BST + c4] = q;
            }
            __syncthreads();
            if (c < 7) {   // prefetch chunk c+1
                const float4* p = (const float4*)(W2 + (c + 1) * 32 * HDIM);
                #pragma unroll
                for (int j = 0; j < 8; j++) stg[j] = p[tid + 256 * j];
            }
            // mma on chunk c
            #pragma unroll
            for (int ks = 0; ks < 4; ks++) {
                const int kcol = ((c << 2) + ks) << 3;   // global permuted-group base
                uint32_t A0[4], A1[4], A2[4], A3[4];
                #pragma unroll
                for (int mt = 0; mt < 4; mt++) {
                    const uint32_t* r0 = &smA[(16 * mt + g) * AST + kcol + 2 * tig];
                    uint2 u0 = *(const uint2*)r0;
                    uint2 u1 = *(const uint2*)(r0 + 8 * AST);
                    A0[mt] = u0.x; A2[mt] = u0.y;
                    A1[mt] = u1.x; A3[mt] = u1.y;
                }
                #pragma unroll
                for (int nt = 0; nt < 4; nt++) {
                    int col = 32 * w + 8 * nt + g;
                    uint32_t B0 = buf[(8 * ks + tig) * BST + col];
                    uint32_t B1 = buf[(8 * ks + tig + 4) * BST + col];
                    #pragma unroll
                    for (int mt = 0; mt < 4; mt++)
                        MMA_TF32(acc1[mt][nt], A0[mt], A1[mt], A2[mt], A3[mt], B0, B1);
                }
            }
            // forward layer-2 partial from same chunk
            #pragma unroll 8
            for (int kk = 0; kk < 32; kk++)
                accH += s_h1[32 * c + kk] * __uint_as_float(buf[kk * BST + tid]);
            // single sync per iter (double buffered): done at top of next iter
        }

        // ---- d2 ----
        {
            float t = tanhf(accH);
            s_d2[tid] = 1.0f - t * t;
        }
        __syncthreads();   // all A reads done; d2 visible

        // ---- write T' = T * d2[l] into smA (tf32, permuted l cols) ----
        #pragma unroll
        for (int mt = 0; mt < 4; mt++)
            #pragma unroll
            for (int nt = 0; nt < 4; nt++)
                #pragma unroll
                for (int c = 0; c < 4; c++) {
                    int r = 2 * tig + (c & 1);
                    int l = 32 * w + 8 * nt + r;
                    int p = (r < 4) ? 2 * r : 2 * (r - 4) + 1;
                    int i = 16 * mt + g + ((c >> 1) << 3);
                    smA[i * AST + 32 * w + 8 * nt + p] =
                        f2tf32(acc1[mt][nt][c] * s_d2[l]);
                }
        __syncthreads();

        // ---- GEMM2: J = T' @ W3  (M=64, N=64, K=256) ----
        const int mt2 = w & 3;          // m-tile 0..3
        const int nh  = w >> 1 & 2;     // unused pattern guard (see below)
        const int nhh = w >> 2;         // n-half 0..1
        (void)nh;
        float acc2[4][4];
        #pragma unroll
        for (int nt = 0; nt < 4; nt++)
            #pragma unroll
            for (int c = 0; c < 4; c++) acc2[nt][c] = 0.0f;

        #pragma unroll 4
        for (int ks = 0; ks < 32; ks++) {
            const int lcol = ks << 3;
            const uint32_t* r0 = &smA[(16 * mt2 + g) * AST + lcol + 2 * tig];
            uint2 u0 = *(const uint2*)r0;
            uint2 u1 = *(const uint2*)(r0 + 8 * AST);
            #pragma unroll
            for (int nt = 0; nt < 4; nt++) {
                int o = 32 * nhh + 8 * nt + g;
                uint2 ub = *(const uint2*)&smW3[o * W3ST + lcol + 2 * tig];
                MMA_TF32(acc2[nt], u0.x, u1.x, u0.y, u1.y, ub.x, ub.y);
            }
        }

        // ---- stage J[o][i] in smem (fp32), then coalesced STG ----
        float* smJ = smBf;   // chunk buffers free now
        #pragma unroll
        for (int nt = 0; nt < 4; nt++)
            #pragma unroll
            for (int c = 0; c < 4; c++) {
                int o = 32 * nhh + 8 * nt + 2 * tig + (c & 1);
                int i = 16 * mt2 + g + ((c >> 1) << 3);
                smJ[o * JST + i] = acc2[nt][c];
            }
        __syncthreads();

        float* ob = out + (size_t)b * (DDIM * DDIM);
        #pragma unroll
        for (int j = 0; j < 4; j++) {
            int f = tid + 256 * j;        // 1024 float4
            int o = f >> 4, i4 = (f & 15) << 2;
            float4 v = *(float4*)&smJ[o * JST + i4];
            *(float4*)&ob[o * DDIM + i4] = v;
        }
        // loop-top sync protects smJ reads vs next batch's W1 stage
    }
}

extern "C" void kernel_launch(void* const* d_in, const int* in_sizes, int n_in,
                              void* d_out, int out_size)
{
    const float* x  = (const float*)d_in[0];
    const float* W1 = (const float*)d_in[1];
    const float* b1 = (const float*)d_in[2];
    const float* W2 = (const float*)d_in[3];
    const float* b2 = (const float*)d_in[4];
    const float* W3 = (const float*)d_in[5];
    float* out = (float*)d_out;

    size_t smem = (size_t)SM_WORDS * sizeof(uint32_t);   // ~200 KB
    cudaFuncSetAttribute(jac_tc_kernel, cudaFuncAttributeMaxDynamicSharedMemorySize, (int)smem);
    jac_tc_kernel<<<NCTA, 256, smem>>>(x, W1, b1, W2, b2, W3, out);
}